// round 5
// baseline (speedup 1.0000x reference)
#include <cuda_runtime.h>
#include <cstdint>

#define NVV 6890
#define NFF 13776
#define NBB 2
#define WN_SPLITS 6
#define TRI_PER_SPLIT (NFF / WN_SPLITS)   // 2296 exactly
#define TRI_CHUNK 128
#define PT_BLK 256
#define JSPLIT 8
#define JMAX 862                           // max split length of NVV/JSPLIT

#define F_INF __int_as_float(0x7f800000)
#define INV_2PI 0.15915494309189535f

// -------- device scratch (no allocations allowed) --------
__device__ float4 g_tri[NBB * NFF * 3];                 // gathered triangles
__device__ float  g_wn_part[NBB * WN_SPLITS * NVV];     // partial atan2 sums
__device__ float  g_d2_part[JSPLIT * NBB * NVV];        // partial min d2
__device__ int    g_mask_u8;                            // 1 if geomask is 1-byte

// -------- detect geomask element width (bool/u8 vs int32) --------
__global__ void detect_mask_kernel(const unsigned* __restrict__ mask) {
    int u8 = 0;
    for (int k = 0; k < 64; ++k) {
        if (mask[k] > 1u) { u8 = 1; break; }
    }
    g_mask_u8 = u8;
}

// -------- gather triangles: g_tri[b][f] = vertices[b][faces[f]] --------
__global__ void gather_kernel(const float* __restrict__ verts,
                              const int* __restrict__ faces) {
    int idx = blockIdx.x * blockDim.x + threadIdx.x;
    if (idx >= NBB * NFF) return;
    int b = idx / NFF, f = idx - b * NFF;
    const float* V = verts + (size_t)b * NVV * 3;
    int i0 = faces[3 * f + 0];
    int i1 = faces[3 * f + 1];
    int i2 = faces[3 * f + 2];
    g_tri[idx * 3 + 0] = make_float4(V[3 * i0], V[3 * i0 + 1], V[3 * i0 + 2], 0.f);
    g_tri[idx * 3 + 1] = make_float4(V[3 * i1], V[3 * i1 + 1], V[3 * i1 + 2], 0.f);
    g_tri[idx * 3 + 2] = make_float4(V[3 * i2], V[3 * i2 + 1], V[3 * i2 + 2], 0.f);
}

// -------- winding numbers: partial atan2 sums --------
__global__ void __launch_bounds__(PT_BLK)
wn_kernel(const float* __restrict__ verts) {
    __shared__ float4 sh[TRI_CHUNK * 3];
    int b = blockIdx.z;
    int split = blockIdx.y;
    int pt = blockIdx.x * PT_BLK + threadIdx.x;
    bool valid = pt < NVV;
    float px = 0.f, py = 0.f, pz = 0.f;
    if (valid) {
        const float* P = verts + ((size_t)b * NVV + pt) * 3;
        px = P[0]; py = P[1]; pz = P[2];
    }
    const float4* tri = g_tri + ((size_t)b * NFF + (size_t)split * TRI_PER_SPLIT) * 3;
    float acc = 0.f;

    for (int c0 = 0; c0 < TRI_PER_SPLIT; c0 += TRI_CHUNK) {
        int cnt = min(TRI_CHUNK, TRI_PER_SPLIT - c0);
        int nv4 = cnt * 3;
        for (int k = threadIdx.x; k < nv4; k += PT_BLK) sh[k] = tri[c0 * 3 + k];
        __syncthreads();
        #pragma unroll 8
        for (int t = 0; t < cnt; ++t) {
            float4 q0 = sh[3 * t + 0];
            float4 q1 = sh[3 * t + 1];
            float4 q2 = sh[3 * t + 2];
            float ax = q0.x - px, ay = q0.y - py, az = q0.z - pz;
            float bx = q1.x - px, by = q1.y - py, bz = q1.z - pz;
            float cx = q2.x - px, cy = q2.y - py, cz = q2.z - pz;
            // cross(b, c)
            float crx = by * cz - bz * cy;
            float cry = bz * cx - bx * cz;
            float crz = bx * cy - by * cx;
            float det = ax * crx + ay * cry + az * crz;
            float na = sqrtf(ax * ax + ay * ay + az * az);
            float nb = sqrtf(bx * bx + by * by + bz * bz);
            float nc = sqrtf(cx * cx + cy * cy + cz * cz);
            float ab = ax * bx + ay * by + az * bz;
            float bc = bx * cx + by * cy + bz * cz;
            float ca = cx * ax + cy * ay + cz * az;
            float denom = na * nb * nc + ab * nc + bc * na + ca * nb;
            acc += atan2f(det, denom);
        }
        __syncthreads();
    }
    if (valid) g_wn_part[((size_t)b * WN_SPLITS + split) * NVV + pt] = acc;
}

// -------- reduce winding-number partials -> exterior --------
__global__ void wn_reduce_kernel(float* __restrict__ out) {
    int idx = blockIdx.x * blockDim.x + threadIdx.x;
    if (idx >= NBB * NVV) return;
    int b = idx / NVV, v = idx - b * NVV;
    float s = 0.f;
    #pragma unroll
    for (int k = 0; k < WN_SPLITS; ++k)
        s += g_wn_part[((size_t)b * WN_SPLITS + k) * NVV + v];
    float wn = s * INV_2PI;   // (2*sum)/(4*pi)
    out[2 * NBB * NVV + idx] = (wn <= 0.99f) ? 1.f : 0.f;
}

// -------- pairwise min distance (both batches fused; j-split partials) -----
// Semantics (from reference): argmin over axis 1 then gather along axis 2
//   => v2v_min[b, i] = min over j with geomask[j, i] of d(j, i).
__global__ void __launch_bounds__(256)
dist_kernel(const float* __restrict__ verts, const void* __restrict__ maskp) {
    __shared__ float4 sv[NBB][JMAX];   // (x, y, z, |v|^2)
    int split = blockIdx.y;
    int jb = (split * NVV) / JSPLIT;
    int je = ((split + 1) * NVV) / JSPLIT;
    int len = je - jb;

    for (int k = threadIdx.x; k < NBB * len; k += 256) {
        int bb = k / len, jl = k - bb * len;
        const float* Vp = verts + ((size_t)bb * NVV + jb + jl) * 3;
        float x = Vp[0], y = Vp[1], z = Vp[2];
        sv[bb][jl] = make_float4(x, y, z, x * x + y * y + z * z);
    }
    __syncthreads();

    int i = blockIdx.x * 256 + threadIdx.x;
    if (i >= NVV) return;

    const float* P0 = verts + (size_t)i * 3;
    const float* P1 = verts + ((size_t)NVV + i) * 3;
    float p0x = P0[0], p0y = P0[1], p0z = P0[2];
    float p1x = P1[0], p1y = P1[1], p1z = P1[2];
    float sq0 = p0x * p0x + p0y * p0y + p0z * p0z;
    float sq1 = p1x * p1x + p1y * p1y + p1z * p1z;
    float m0 = F_INF, m1 = F_INF;

    if (g_mask_u8) {
        const unsigned char* m8 = (const unsigned char*)maskp;
        for (int jl = 0; jl < len; ++jl) {
            size_t j = (size_t)(jb + jl);
            bool ms = m8[j * NVV + i] != 0;
            float4 v0 = sv[0][jl];
            float d0 = p0x * v0.x + p0y * v0.y + p0z * v0.z;
            float d20 = sq0 + v0.w - 2.f * d0;
            if (ms && d20 < m0) m0 = d20;
            float4 v1 = sv[1][jl];
            float d1 = p1x * v1.x + p1y * v1.y + p1z * v1.z;
            float d21 = sq1 + v1.w - 2.f * d1;
            if (ms && d21 < m1) m1 = d21;
        }
    } else {
        const int* m32 = (const int*)maskp;
        for (int jl = 0; jl < len; ++jl) {
            size_t j = (size_t)(jb + jl);
            bool ms = m32[j * NVV + i] != 0;
            float4 v0 = sv[0][jl];
            float d0 = p0x * v0.x + p0y * v0.y + p0z * v0.z;
            float d20 = sq0 + v0.w - 2.f * d0;
            if (ms && d20 < m0) m0 = d20;
            float4 v1 = sv[1][jl];
            float d1 = p1x * v1.x + p1y * v1.y + p1z * v1.z;
            float d21 = sq1 + v1.w - 2.f * d1;
            if (ms && d21 < m1) m1 = d21;
        }
    }
    g_d2_part[((size_t)split * NBB + 0) * NVV + i] = m0;
    g_d2_part[((size_t)split * NBB + 1) * NVV + i] = m1;
}

// -------- reduce distance partials -> v2v_min, incontact --------
__global__ void dist_reduce_kernel(const float* __restrict__ verts,
                                   float* __restrict__ out) {
    int idx = blockIdx.x * blockDim.x + threadIdx.x;
    if (idx >= NBB * NVV) return;
    int b = idx / NVV, v = idx - b * NVV;
    float m = F_INF;
    #pragma unroll
    for (int k = 0; k < JSPLIT; ++k)
        m = fminf(m, g_d2_part[((size_t)k * NBB + b) * NVV + v]);
    if (isinf(m)) {
        // fully-masked column: reference argmin of all-inf returns index 0
        const float* Pv = verts + ((size_t)b * NVV + v) * 3;
        const float* P0 = verts + (size_t)b * NVV * 3;
        float sqv = Pv[0] * Pv[0] + Pv[1] * Pv[1] + Pv[2] * Pv[2];
        float sq0 = P0[0] * P0[0] + P0[1] * P0[1] + P0[2] * P0[2];
        float dot = Pv[0] * P0[0] + Pv[1] * P0[1] + Pv[2] * P0[2];
        m = sqv + sq0 - 2.f * dot;
    }
    float d = sqrtf(fmaxf(m, 1e-12f));
    out[idx] = d;
    out[NBB * NVV + idx] = (d < 0.02f) ? 1.f : 0.f;
}

extern "C" void kernel_launch(void* const* d_in, const int* in_sizes, int n_in,
                              void* d_out, int out_size) {
    const float* verts = (const float*)d_in[0];
    const int*   faces = (const int*)d_in[1];
    const void*  mask  = d_in[2];
    float* out = (float*)d_out;

    detect_mask_kernel<<<1, 1>>>((const unsigned*)mask);

    gather_kernel<<<(NBB * NFF + 255) / 256, 256>>>(verts, faces);

    dim3 wg((NVV + PT_BLK - 1) / PT_BLK, WN_SPLITS, NBB);
    wn_kernel<<<wg, PT_BLK>>>(verts);

    wn_reduce_kernel<<<(NBB * NVV + 255) / 256, 256>>>(out);

    dim3 dg((NVV + 255) / 256, JSPLIT);
    dist_kernel<<<dg, 256>>>(verts, mask);

    dist_reduce_kernel<<<(NBB * NVV + 255) / 256, 256>>>(verts, out);
}

// round 6
// speedup vs baseline: 1.2940x; 1.2940x over previous
#include <cuda_runtime.h>
#include <cstdint>

#define NVV 6890
#define NFF 13776
#define NBB 2
#define WN_SPLITS 6
#define TRI_PER_SPLIT (NFF / WN_SPLITS)   // 2296 exactly
#define TRI_CHUNK 128
#define PT_BLK 256
#define JSPLIT 8
#define JMAX 862                           // max split length of NVV/JSPLIT

#define F_INF __int_as_float(0x7f800000)
#define INV_2PI 0.15915494309189535f

// -------- device scratch (no allocations allowed) --------
__device__ float4 g_tri[NBB * NFF * 3];                 // gathered triangles
__device__ float  g_wn_part[NBB * WN_SPLITS * NVV];     // partial atan2 sums
__device__ float  g_d2_part[JSPLIT * NBB * NVV];        // partial min d2
__device__ int    g_mask_u8;                            // 1 if geomask is 1-byte

// -------- fast approx helpers --------
__device__ __forceinline__ float fsqrt_approx(float x) {
    float r;
    asm("sqrt.approx.f32 %0, %1;" : "=f"(r) : "f"(x));
    return r;   // sqrt.approx(0) == 0 exactly; ~22-bit accurate
}

__device__ __forceinline__ float frcp_approx(float x) {
    float r;
    asm("rcp.approx.f32 %0, %1;" : "=f"(r) : "f"(x));
    return r;
}

// Branch-free atan2, max err ~1e-7 rad. Matches numpy zero/sign conventions:
//   atan2(+-0, +0) = +-0 ; atan2(+-0, -x) = +-pi ; atan2(y, 0) = +-pi/2.
__device__ __forceinline__ float fast_atan2f(float y, float x) {
    float ax = fabsf(x), ay = fabsf(y);
    float mx = fmaxf(ax, ay), mn = fminf(ax, ay);
    float t = mn * frcp_approx(mx);
    // guard zero/denormal mx (MUFU.RCP is FTZ): exact-vertex case -> angle 0
    t = (mx < 1.17549435e-38f) ? 0.0f : t;
    float s = t * t;
    float r =               2.78569828e-3f;
    r = fmaf(r, s, -1.58660226e-2f);
    r = fmaf(r, s,  4.24722321e-2f);
    r = fmaf(r, s, -7.49753043e-2f);
    r = fmaf(r, s,  1.06448799e-1f);
    r = fmaf(r, s, -1.42070308e-1f);
    r = fmaf(r, s,  1.99934542e-1f);
    r = fmaf(r, s, -3.33331466e-1f);
    r = r * s;
    r = fmaf(r, t, t);                     // atan(t), t in [0,1]
    r = (ay > ax) ? (1.57079637f - r) : r; // octant: |y|>|x|
    r = signbit(x) ? (3.14159274f - r) : r;// left half-plane (incl. -0)
    return copysignf(r, y);
}

// -------- detect geomask element width (bool/u8 vs int32) --------
__global__ void detect_mask_kernel(const unsigned* __restrict__ mask) {
    int u8 = 0;
    for (int k = 0; k < 64; ++k) {
        if (mask[k] > 1u) { u8 = 1; break; }
    }
    g_mask_u8 = u8;
}

// -------- gather triangles: g_tri[b][f] = vertices[b][faces[f]] --------
__global__ void gather_kernel(const float* __restrict__ verts,
                              const int* __restrict__ faces) {
    int idx = blockIdx.x * blockDim.x + threadIdx.x;
    if (idx >= NBB * NFF) return;
    int b = idx / NFF, f = idx - b * NFF;
    const float* V = verts + (size_t)b * NVV * 3;
    int i0 = faces[3 * f + 0];
    int i1 = faces[3 * f + 1];
    int i2 = faces[3 * f + 2];
    g_tri[idx * 3 + 0] = make_float4(V[3 * i0], V[3 * i0 + 1], V[3 * i0 + 2], 0.f);
    g_tri[idx * 3 + 1] = make_float4(V[3 * i1], V[3 * i1 + 1], V[3 * i1 + 2], 0.f);
    g_tri[idx * 3 + 2] = make_float4(V[3 * i2], V[3 * i2 + 1], V[3 * i2 + 2], 0.f);
}

// -------- winding numbers: partial atan2 sums --------
__global__ void __launch_bounds__(PT_BLK)
wn_kernel(const float* __restrict__ verts) {
    __shared__ float4 sh[TRI_CHUNK * 3];
    int b = blockIdx.z;
    int split = blockIdx.y;
    int pt = blockIdx.x * PT_BLK + threadIdx.x;
    bool valid = pt < NVV;
    float px = 0.f, py = 0.f, pz = 0.f;
    if (valid) {
        const float* P = verts + ((size_t)b * NVV + pt) * 3;
        px = P[0]; py = P[1]; pz = P[2];
    }
    const float4* tri = g_tri + ((size_t)b * NFF + (size_t)split * TRI_PER_SPLIT) * 3;
    float acc = 0.f;

    for (int c0 = 0; c0 < TRI_PER_SPLIT; c0 += TRI_CHUNK) {
        int cnt = min(TRI_CHUNK, TRI_PER_SPLIT - c0);
        int nv4 = cnt * 3;
        for (int k = threadIdx.x; k < nv4; k += PT_BLK) sh[k] = tri[c0 * 3 + k];
        __syncthreads();
        #pragma unroll 8
        for (int t = 0; t < cnt; ++t) {
            float4 q0 = sh[3 * t + 0];
            float4 q1 = sh[3 * t + 1];
            float4 q2 = sh[3 * t + 2];
            float ax = q0.x - px, ay = q0.y - py, az = q0.z - pz;
            float bx = q1.x - px, by = q1.y - py, bz = q1.z - pz;
            float cx = q2.x - px, cy = q2.y - py, cz = q2.z - pz;
            // cross(b, c)
            float crx = by * cz - bz * cy;
            float cry = bz * cx - bx * cz;
            float crz = bx * cy - by * cx;
            float det = ax * crx + ay * cry + az * crz;
            float na = fsqrt_approx(ax * ax + ay * ay + az * az);
            float nb = fsqrt_approx(bx * bx + by * by + bz * bz);
            float nc = fsqrt_approx(cx * cx + cy * cy + cz * cz);
            float ab = ax * bx + ay * by + az * bz;
            float bc = bx * cx + by * cy + bz * cz;
            float ca = cx * ax + cy * ay + cz * az;
            float denom = na * nb * nc + ab * nc + bc * na + ca * nb;
            acc += fast_atan2f(det, denom);
        }
        __syncthreads();
    }
    if (valid) g_wn_part[((size_t)b * WN_SPLITS + split) * NVV + pt] = acc;
}

// -------- reduce winding-number partials -> exterior --------
__global__ void wn_reduce_kernel(float* __restrict__ out) {
    int idx = blockIdx.x * blockDim.x + threadIdx.x;
    if (idx >= NBB * NVV) return;
    int b = idx / NVV, v = idx - b * NVV;
    float s = 0.f;
    #pragma unroll
    for (int k = 0; k < WN_SPLITS; ++k)
        s += g_wn_part[((size_t)b * WN_SPLITS + k) * NVV + v];
    float wn = s * INV_2PI;   // (2*sum)/(4*pi)
    out[2 * NBB * NVV + idx] = (wn <= 0.99f) ? 1.f : 0.f;
}

// -------- pairwise min distance (both batches fused; j-split partials) -----
// Semantics (from reference): argmin over axis 1 then gather along axis 2
//   => v2v_min[b, i] = min over j with geomask[j, i] of d(j, i).
__global__ void __launch_bounds__(256)
dist_kernel(const float* __restrict__ verts, const void* __restrict__ maskp) {
    __shared__ float4 sv[NBB][JMAX];   // (x, y, z, |v|^2)
    int split = blockIdx.y;
    int jb = (split * NVV) / JSPLIT;
    int je = ((split + 1) * NVV) / JSPLIT;
    int len = je - jb;

    for (int k = threadIdx.x; k < NBB * len; k += 256) {
        int bb = k / len, jl = k - bb * len;
        const float* Vp = verts + ((size_t)bb * NVV + jb + jl) * 3;
        float x = Vp[0], y = Vp[1], z = Vp[2];
        sv[bb][jl] = make_float4(x, y, z, x * x + y * y + z * z);
    }
    __syncthreads();

    int i = blockIdx.x * 256 + threadIdx.x;
    if (i >= NVV) return;

    const float* P0 = verts + (size_t)i * 3;
    const float* P1 = verts + ((size_t)NVV + i) * 3;
    float p0x = P0[0], p0y = P0[1], p0z = P0[2];
    float p1x = P1[0], p1y = P1[1], p1z = P1[2];
    float sq0 = p0x * p0x + p0y * p0y + p0z * p0z;
    float sq1 = p1x * p1x + p1y * p1y + p1z * p1z;
    float m0 = F_INF, m1 = F_INF;

    if (g_mask_u8) {
        const unsigned char* m8 = (const unsigned char*)maskp;
        for (int jl = 0; jl < len; ++jl) {
            size_t j = (size_t)(jb + jl);
            bool ms = m8[j * NVV + i] != 0;
            float4 v0 = sv[0][jl];
            float d0 = p0x * v0.x + p0y * v0.y + p0z * v0.z;
            float d20 = sq0 + v0.w - 2.f * d0;
            if (ms && d20 < m0) m0 = d20;
            float4 v1 = sv[1][jl];
            float d1 = p1x * v1.x + p1y * v1.y + p1z * v1.z;
            float d21 = sq1 + v1.w - 2.f * d1;
            if (ms && d21 < m1) m1 = d21;
        }
    } else {
        const int* m32 = (const int*)maskp;
        for (int jl = 0; jl < len; ++jl) {
            size_t j = (size_t)(jb + jl);
            bool ms = m32[j * NVV + i] != 0;
            float4 v0 = sv[0][jl];
            float d0 = p0x * v0.x + p0y * v0.y + p0z * v0.z;
            float d20 = sq0 + v0.w - 2.f * d0;
            if (ms && d20 < m0) m0 = d20;
            float4 v1 = sv[1][jl];
            float d1 = p1x * v1.x + p1y * v1.y + p1z * v1.z;
            float d21 = sq1 + v1.w - 2.f * d1;
            if (ms && d21 < m1) m1 = d21;
        }
    }
    g_d2_part[((size_t)split * NBB + 0) * NVV + i] = m0;
    g_d2_part[((size_t)split * NBB + 1) * NVV + i] = m1;
}

// -------- reduce distance partials -> v2v_min, incontact --------
__global__ void dist_reduce_kernel(const float* __restrict__ verts,
                                   float* __restrict__ out) {
    int idx = blockIdx.x * blockDim.x + threadIdx.x;
    if (idx >= NBB * NVV) return;
    int b = idx / NVV, v = idx - b * NVV;
    float m = F_INF;
    #pragma unroll
    for (int k = 0; k < JSPLIT; ++k)
        m = fminf(m, g_d2_part[((size_t)k * NBB + b) * NVV + v]);
    if (isinf(m)) {
        // fully-masked column: reference argmin of all-inf returns index 0
        const float* Pv = verts + ((size_t)b * NVV + v) * 3;
        const float* P0 = verts + (size_t)b * NVV * 3;
        float sqv = Pv[0] * Pv[0] + Pv[1] * Pv[1] + Pv[2] * Pv[2];
        float sq0 = P0[0] * P0[0] + P0[1] * P0[1] + P0[2] * P0[2];
        float dot = Pv[0] * P0[0] + Pv[1] * P0[1] + Pv[2] * P0[2];
        m = sqv + sq0 - 2.f * dot;
    }
    float d = sqrtf(fmaxf(m, 1e-12f));
    out[idx] = d;
    out[NBB * NVV + idx] = (d < 0.02f) ? 1.f : 0.f;
}

extern "C" void kernel_launch(void* const* d_in, const int* in_sizes, int n_in,
                              void* d_out, int out_size) {
    const float* verts = (const float*)d_in[0];
    const int*   faces = (const int*)d_in[1];
    const void*  mask  = d_in[2];
    float* out = (float*)d_out;

    detect_mask_kernel<<<1, 1>>>((const unsigned*)mask);

    gather_kernel<<<(NBB * NFF + 255) / 256, 256>>>(verts, faces);

    dim3 wg((NVV + PT_BLK - 1) / PT_BLK, WN_SPLITS, NBB);
    wn_kernel<<<wg, PT_BLK>>>(verts);

    wn_reduce_kernel<<<(NBB * NVV + 255) / 256, 256>>>(out);

    dim3 dg((NVV + 255) / 256, JSPLIT);
    dist_kernel<<<dg, 256>>>(verts, mask);

    dist_reduce_kernel<<<(NBB * NVV + 255) / 256, 256>>>(verts, out);
}

// round 7
// speedup vs baseline: 1.3351x; 1.0318x over previous
#include <cuda_runtime.h>
#include <cstdint>

#define NVV 6890
#define NFF 13776
#define NBB 2
#define WN_SPLITS 12
#define TRI_PER_SPLIT (NFF / WN_SPLITS)   // 1148 exactly
#define TRI_CHUNK 128
#define PT_BLK 256
#define PT_PER_BLK (PT_BLK * 2)
#define JSPLIT 8
#define JMAX 862                           // max split length of NVV/JSPLIT

#define F_INF __int_as_float(0x7f800000)
#define INV_2PI 0.15915494309189535f

// -------- device scratch (no allocations allowed) --------
__device__ float4 g_tri[NBB * NFF * 3];                 // gathered triangles
__device__ float  g_wn_part[NBB * WN_SPLITS * NVV];     // partial atan2 sums
__device__ float  g_d2_part[JSPLIT * NBB * NVV];        // partial min d2
__device__ int    g_mask_u8;                            // 1 if geomask is 1-byte

// -------- fast approx helpers --------
__device__ __forceinline__ float fsqrt_approx(float x) {
    float r;
    asm("sqrt.approx.f32 %0, %1;" : "=f"(r) : "f"(x));
    return r;   // sqrt.approx(0) == 0 exactly; ~22-bit accurate
}

__device__ __forceinline__ float frcp_approx(float x) {
    float r;
    asm("rcp.approx.f32 %0, %1;" : "=f"(r) : "f"(x));
    return r;
}

// Branch-free atan2, max err ~1e-7 rad. Matches numpy zero/sign conventions.
__device__ __forceinline__ float fast_atan2f(float y, float x) {
    float ax = fabsf(x), ay = fabsf(y);
    float mx = fmaxf(ax, ay), mn = fminf(ax, ay);
    float t = mn * frcp_approx(mx);
    t = (mx < 1.17549435e-38f) ? 0.0f : t;   // FTZ-rcp guard: vertex case -> 0
    float s = t * t;
    float r =               2.78569828e-3f;
    r = fmaf(r, s, -1.58660226e-2f);
    r = fmaf(r, s,  4.24722321e-2f);
    r = fmaf(r, s, -7.49753043e-2f);
    r = fmaf(r, s,  1.06448799e-1f);
    r = fmaf(r, s, -1.42070308e-1f);
    r = fmaf(r, s,  1.99934542e-1f);
    r = fmaf(r, s, -3.33331466e-1f);
    r = r * s;
    r = fmaf(r, t, t);                     // atan(t), t in [0,1]
    r = (ay > ax) ? (1.57079637f - r) : r; // octant: |y|>|x|
    r = signbit(x) ? (3.14159274f - r) : r;// left half-plane (incl. -0)
    return copysignf(r, y);
}

// one point-vs-triangle solid-angle term
__device__ __forceinline__ float wn_eval(float px, float py, float pz,
                                         const float4& q0, const float4& q1,
                                         const float4& q2) {
    float ax = q0.x - px, ay = q0.y - py, az = q0.z - pz;
    float bx = q1.x - px, by = q1.y - py, bz = q1.z - pz;
    float cx = q2.x - px, cy = q2.y - py, cz = q2.z - pz;
    float crx = by * cz - bz * cy;
    float cry = bz * cx - bx * cz;
    float crz = bx * cy - by * cx;
    float det = ax * crx + ay * cry + az * crz;
    float na = fsqrt_approx(ax * ax + ay * ay + az * az);
    float nb = fsqrt_approx(bx * bx + by * by + bz * bz);
    float nc = fsqrt_approx(cx * cx + cy * cy + cz * cz);
    float ab = ax * bx + ay * by + az * bz;
    float bc = bx * cx + by * cy + bz * cz;
    float ca = cx * ax + cy * ay + cz * az;
    float denom = na * nb * nc + ab * nc + bc * na + ca * nb;
    return fast_atan2f(det, denom);
}

// -------- detect geomask element width (bool/u8 vs int32) --------
__global__ void detect_mask_kernel(const unsigned* __restrict__ mask) {
    int u8 = 0;
    for (int k = 0; k < 64; ++k) {
        if (mask[k] > 1u) { u8 = 1; break; }
    }
    g_mask_u8 = u8;
}

// -------- gather triangles: g_tri[b][f] = vertices[b][faces[f]] --------
__global__ void gather_kernel(const float* __restrict__ verts,
                              const int* __restrict__ faces) {
    int idx = blockIdx.x * blockDim.x + threadIdx.x;
    if (idx >= NBB * NFF) return;
    int b = idx / NFF, f = idx - b * NFF;
    const float* V = verts + (size_t)b * NVV * 3;
    int i0 = faces[3 * f + 0];
    int i1 = faces[3 * f + 1];
    int i2 = faces[3 * f + 2];
    g_tri[idx * 3 + 0] = make_float4(V[3 * i0], V[3 * i0 + 1], V[3 * i0 + 2], 0.f);
    g_tri[idx * 3 + 1] = make_float4(V[3 * i1], V[3 * i1 + 1], V[3 * i1 + 2], 0.f);
    g_tri[idx * 3 + 2] = make_float4(V[3 * i2], V[3 * i2 + 1], V[3 * i2 + 2], 0.f);
}

// -------- winding numbers: 2 points/thread, partial atan2 sums --------
__global__ void __launch_bounds__(PT_BLK)
wn_kernel(const float* __restrict__ verts) {
    __shared__ float4 sh[TRI_CHUNK * 3];
    int b = blockIdx.z;
    int split = blockIdx.y;
    int pt0 = blockIdx.x * PT_PER_BLK + threadIdx.x;
    int pt1 = pt0 + PT_BLK;
    bool v0 = pt0 < NVV, v1 = pt1 < NVV;
    float p0x = 0.f, p0y = 0.f, p0z = 0.f;
    float p1x = 0.f, p1y = 0.f, p1z = 0.f;
    if (v0) {
        const float* P = verts + ((size_t)b * NVV + pt0) * 3;
        p0x = P[0]; p0y = P[1]; p0z = P[2];
    }
    if (v1) {
        const float* P = verts + ((size_t)b * NVV + pt1) * 3;
        p1x = P[0]; p1y = P[1]; p1z = P[2];
    }
    const float4* tri = g_tri + ((size_t)b * NFF + (size_t)split * TRI_PER_SPLIT) * 3;
    float acc0 = 0.f, acc1 = 0.f;

    for (int c0 = 0; c0 < TRI_PER_SPLIT; c0 += TRI_CHUNK) {
        int cnt = min(TRI_CHUNK, TRI_PER_SPLIT - c0);
        int nv4 = cnt * 3;
        for (int k = threadIdx.x; k < nv4; k += PT_BLK) sh[k] = tri[c0 * 3 + k];
        __syncthreads();
        #pragma unroll 4
        for (int t = 0; t < cnt; ++t) {
            float4 q0 = sh[3 * t + 0];
            float4 q1 = sh[3 * t + 1];
            float4 q2 = sh[3 * t + 2];
            acc0 += wn_eval(p0x, p0y, p0z, q0, q1, q2);
            acc1 += wn_eval(p1x, p1y, p1z, q0, q1, q2);
        }
        __syncthreads();
    }
    size_t base = ((size_t)b * WN_SPLITS + split) * NVV;
    if (v0) g_wn_part[base + pt0] = acc0;
    if (v1) g_wn_part[base + pt1] = acc1;
}

// -------- reduce winding-number partials -> exterior --------
__global__ void wn_reduce_kernel(float* __restrict__ out) {
    int idx = blockIdx.x * blockDim.x + threadIdx.x;
    if (idx >= NBB * NVV) return;
    int b = idx / NVV, v = idx - b * NVV;
    float s = 0.f;
    #pragma unroll
    for (int k = 0; k < WN_SPLITS; ++k)
        s += g_wn_part[((size_t)b * WN_SPLITS + k) * NVV + v];
    float wn = s * INV_2PI;   // (2*sum)/(4*pi)
    out[2 * NBB * NVV + idx] = (wn <= 0.99f) ? 1.f : 0.f;
}

// -------- pairwise min distance (both batches fused; j-split partials) -----
// v2v_min[b, i] = min over j with geomask[j, i] of d(j, i).
__global__ void __launch_bounds__(256)
dist_kernel(const float* __restrict__ verts, const void* __restrict__ maskp) {
    __shared__ float4 sv[NBB][JMAX];   // (x, y, z, |v|^2)
    int split = blockIdx.y;
    int jb = (split * NVV) / JSPLIT;
    int je = ((split + 1) * NVV) / JSPLIT;
    int len = je - jb;

    for (int k = threadIdx.x; k < NBB * len; k += 256) {
        int bb = k / len, jl = k - bb * len;
        const float* Vp = verts + ((size_t)bb * NVV + jb + jl) * 3;
        float x = Vp[0], y = Vp[1], z = Vp[2];
        sv[bb][jl] = make_float4(x, y, z, x * x + y * y + z * z);
    }
    __syncthreads();

    int i = blockIdx.x * 256 + threadIdx.x;
    if (i >= NVV) return;

    const float* P0 = verts + (size_t)i * 3;
    const float* P1 = verts + ((size_t)NVV + i) * 3;
    float p0x = P0[0], p0y = P0[1], p0z = P0[2];
    float p1x = P1[0], p1y = P1[1], p1z = P1[2];
    float sq0 = p0x * p0x + p0y * p0y + p0z * p0z;
    float sq1 = p1x * p1x + p1y * p1y + p1z * p1z;
    float m0 = F_INF, m1 = F_INF;

    if (g_mask_u8) {
        const unsigned char* m8 = (const unsigned char*)maskp;
        for (int jl = 0; jl < len; ++jl) {
            size_t j = (size_t)(jb + jl);
            bool ms = m8[j * NVV + i] != 0;
            float4 v0 = sv[0][jl];
            float d0 = p0x * v0.x + p0y * v0.y + p0z * v0.z;
            float d20 = sq0 + v0.w - 2.f * d0;
            if (ms && d20 < m0) m0 = d20;
            float4 v1 = sv[1][jl];
            float d1 = p1x * v1.x + p1y * v1.y + p1z * v1.z;
            float d21 = sq1 + v1.w - 2.f * d1;
            if (ms && d21 < m1) m1 = d21;
        }
    } else {
        const int* m32 = (const int*)maskp;
        for (int jl = 0; jl < len; ++jl) {
            size_t j = (size_t)(jb + jl);
            bool ms = m32[j * NVV + i] != 0;
            float4 v0 = sv[0][jl];
            float d0 = p0x * v0.x + p0y * v0.y + p0z * v0.z;
            float d20 = sq0 + v0.w - 2.f * d0;
            if (ms && d20 < m0) m0 = d20;
            float4 v1 = sv[1][jl];
            float d1 = p1x * v1.x + p1y * v1.y + p1z * v1.z;
            float d21 = sq1 + v1.w - 2.f * d1;
            if (ms && d21 < m1) m1 = d21;
        }
    }
    g_d2_part[((size_t)split * NBB + 0) * NVV + i] = m0;
    g_d2_part[((size_t)split * NBB + 1) * NVV + i] = m1;
}

// -------- reduce distance partials -> v2v_min, incontact --------
__global__ void dist_reduce_kernel(const float* __restrict__ verts,
                                   float* __restrict__ out) {
    int idx = blockIdx.x * blockDim.x + threadIdx.x;
    if (idx >= NBB * NVV) return;
    int b = idx / NVV, v = idx - b * NVV;
    float m = F_INF;
    #pragma unroll
    for (int k = 0; k < JSPLIT; ++k)
        m = fminf(m, g_d2_part[((size_t)k * NBB + b) * NVV + v]);
    if (isinf(m)) {
        const float* Pv = verts + ((size_t)b * NVV + v) * 3;
        const float* P0 = verts + (size_t)b * NVV * 3;
        float sqv = Pv[0] * Pv[0] + Pv[1] * Pv[1] + Pv[2] * Pv[2];
        float sq0 = P0[0] * P0[0] + P0[1] * P0[1] + P0[2] * P0[2];
        float dot = Pv[0] * P0[0] + Pv[1] * P0[1] + Pv[2] * P0[2];
        m = sqv + sq0 - 2.f * dot;
    }
    float d = sqrtf(fmaxf(m, 1e-12f));
    out[idx] = d;
    out[NBB * NVV + idx] = (d < 0.02f) ? 1.f : 0.f;
}

extern "C" void kernel_launch(void* const* d_in, const int* in_sizes, int n_in,
                              void* d_out, int out_size) {
    const float* verts = (const float*)d_in[0];
    const int*   faces = (const int*)d_in[1];
    const void*  mask  = d_in[2];
    float* out = (float*)d_out;

    detect_mask_kernel<<<1, 1>>>((const unsigned*)mask);

    gather_kernel<<<(NBB * NFF + 255) / 256, 256>>>(verts, faces);

    dim3 wg((NVV + PT_PER_BLK - 1) / PT_PER_BLK, WN_SPLITS, NBB);
    wn_kernel<<<wg, PT_BLK>>>(verts);

    wn_reduce_kernel<<<(NBB * NVV + 255) / 256, 256>>>(out);

    dim3 dg((NVV + 255) / 256, JSPLIT);
    dist_kernel<<<dg, 256>>>(verts, mask);

    dist_reduce_kernel<<<(NBB * NVV + 255) / 256, 256>>>(verts, out);
}